// round 16
// baseline (speedup 1.0000x reference)
#include <cuda_runtime.h>
#include <cuda_pipeline.h>
#include <math.h>

// Problem constants
#define NN   2000
#define CC   4
#define LL   5000
#define EE   64000
#define HH   512
#define RP   207
#define L2O  1248          // (5000-11)/4+1
#define KT   32            // GEMM k-tile

typedef unsigned long long u64;

// ---------------- f32x2 packed helpers ---------------------------------------
__device__ __forceinline__ u64 pk2(float lo, float hi) {
    u64 r; asm("mov.b64 %0, {%1, %2};" : "=l"(r) : "f"(lo), "f"(hi)); return r;
}
__device__ __forceinline__ void upk2(u64 v, float& lo, float& hi) {
    asm("mov.b64 {%0, %1}, %2;" : "=f"(lo), "=f"(hi) : "l"(v));
}
__device__ __forceinline__ u64 fma2(u64 a, u64 b, u64 c) {
    u64 d; asm("fma.rn.f32x2 %0, %1, %2, %3;" : "=l"(d) : "l"(a), "l"(b), "l"(c));
    return d;
}

// ---------------- scratch (device globals; no runtime allocation) ------------
__device__ float g_feat[NN*RP];
__device__ float g_h  [NN*HH];
__device__ float g_z  [NN*HH];
__device__ float g_xl [NN*HH];
__device__ int   g_cnt [NN];
__device__ int   g_off [NN];
__device__ int   g_cur [NN];
__device__ int   g_esrc[EE];
__device__ float g_dinv[NN];
__device__ float g_colsum[HH];
__device__ float g_colsq [HH];

// ---------------- fused conv pipeline: x -> feat (per-node block) ------------
__global__ __launch_bounds__(256, 2)
void conv_feat_kernel(const float* __restrict__ x,
                      const float* __restrict__ w1, const float* __restrict__ b1,
                      const float* __restrict__ w2, const float* __restrict__ b2,
                      const float* __restrict__ w3, const float* __restrict__ b3)
{
    __shared__ __align__(16) float4 sw1q[16];
    __shared__ float sb1[16];
    __shared__ __align__(16) float4 sw2q[4][11];
    __shared__ float sb2[4];
    __shared__ float sw3[4][11];
    __shared__ float sb3;
    __shared__ __align__(16) float y2s[4][L2O];

    const int n    = blockIdx.x;
    const int tid  = threadIdx.x;
    const int warp = tid >> 5;
    const int lane = tid & 31;

    if (tid < 16) {
        sw1q[tid] = make_float4(w1[tid*4+0], w1[tid*4+1], w1[tid*4+2], w1[tid*4+3]);
        sb1[tid]  = b1[tid];
    }
    if (tid < 44) {
        const int c = tid / 11, k = tid % 11;
        sw2q[c][k] = make_float4(w2[0*44 + c*11 + k], w2[1*44 + c*11 + k],
                                 w2[2*44 + c*11 + k], w2[3*44 + c*11 + k]);
        sw3[c][k] = w3[tid];
    }
    if (tid < 4)   sb2[tid] = b2[tid];
    if (tid == 0)  sb3 = b3[0];
    __syncthreads();

    const float* xn = x + (size_t)n * CC * LL;

    float4 xv[4];
    {
        const int p0 = 4*(warp*30 + lane);
        const bool ld = (p0 + 3) < LL;
        #pragma unroll
        for (int c = 0; c < 4; c++)
            xv[c] = ld ? *(const float4*)&xn[c*LL + p0]
                       : make_float4(0.f, 0.f, 0.f, 0.f);
    }

    #pragma unroll 1
    for (int it = 0; it < 6; it++) {
        const int seg = it*240 + warp*30;
        const int t   = seg + lane;

        float4 xnext[4];
        if (it < 5) {
            const int p1 = 4*((it+1)*240 + warp*30 + lane);
            const bool ld1 = (p1 + 3) < LL;
            #pragma unroll
            for (int c = 0; c < 4; c++)
                xnext[c] = ld1 ? *(const float4*)&xn[c*LL + p1]
                               : make_float4(0.f, 0.f, 0.f, 0.f);
        }

        float h[4][4];
        #pragma unroll
        for (int j = 0; j < 4; j++) {
            const float x0 = ((const float*)&xv[0])[j];
            const float x1 = ((const float*)&xv[1])[j];
            const float x2 = ((const float*)&xv[2])[j];
            const float x3 = ((const float*)&xv[3])[j];
            #pragma unroll
            for (int a = 0; a < 4; a++) {
                float mx = -3.4e38f;
                #pragma unroll
                for (int b = 0; b < 4; b++) {
                    const int o = a*4 + b;
                    const float4 w = sw1q[o];
                    float pre = sb1[o];
                    pre = fmaf(x0, w.x, pre);
                    pre = fmaf(x1, w.y, pre);
                    pre = fmaf(x2, w.z, pre);
                    pre = fmaf(x3, w.w, pre);
                    mx = fmaxf(mx, pre);
                }
                h[a][j] = fmaxf(mx, 0.f);
            }
        }

        const bool emit = (lane < 30) && (t < L2O);
        float acc0 = sb2[0], acc1 = sb2[1], acc2 = sb2[2], acc3 = sb2[3];
        #pragma unroll
        for (int a = 0; a < 4; a++) {
            float hv[11];
            hv[0] = h[a][0]; hv[1] = h[a][1]; hv[2] = h[a][2]; hv[3] = h[a][3];
            hv[4]  = __shfl_down_sync(0xffffffffu, h[a][0], 1);
            hv[5]  = __shfl_down_sync(0xffffffffu, h[a][1], 1);
            hv[6]  = __shfl_down_sync(0xffffffffu, h[a][2], 1);
            hv[7]  = __shfl_down_sync(0xffffffffu, h[a][3], 1);
            hv[8]  = __shfl_down_sync(0xffffffffu, h[a][0], 2);
            hv[9]  = __shfl_down_sync(0xffffffffu, h[a][1], 2);
            hv[10] = __shfl_down_sync(0xffffffffu, h[a][2], 2);
            #pragma unroll
            for (int k = 0; k < 11; k++) {
                const float4 wq = sw2q[a][k];
                acc0 = fmaf(hv[k], wq.x, acc0);
                acc1 = fmaf(hv[k], wq.y, acc1);
                acc2 = fmaf(hv[k], wq.z, acc2);
                acc3 = fmaf(hv[k], wq.w, acc3);
            }
        }
        if (emit) {
            y2s[0][t] = fmaxf(acc0, 0.f);
            y2s[1][t] = fmaxf(acc1, 0.f);
            y2s[2][t] = fmaxf(acc2, 0.f);
            y2s[3][t] = fmaxf(acc3, 0.f);
        }

        #pragma unroll
        for (int c = 0; c < 4; c++) xv[c] = xnext[c];
    }
    __syncthreads();

    for (int t = tid; t < RP; t += 256) {
        float acc = sb3;
        #pragma unroll
        for (int c = 0; c < 4; c++)
            #pragma unroll
            for (int k = 0; k < 11; k++)
                acc = fmaf(y2s[c][6*t + k], sw3[c][k], acc);
        g_feat[(size_t)n*RP + t] = fmaxf(acc, 0.f);
    }
}

// ---------------- CSR build ---------------------------------------------------
__global__ void csr_init_kernel() {
    int i = blockIdx.x*blockDim.x + threadIdx.x;
    if (i < NN) g_cnt[i] = 0;
    if (i < HH) { g_colsum[i] = 0.f; g_colsq[i] = 0.f; }
}
__global__ void csr_count_kernel(const int* __restrict__ dst) {
    int e = blockIdx.x*blockDim.x + threadIdx.x;
    if (e < EE) atomicAdd(&g_cnt[dst[e]], 1);
}
__global__ __launch_bounds__(256)
void csr_scan_kernel() {
    __shared__ int tsum[256];
    __shared__ int wsum[8];
    const int t = threadIdx.x;
    const int base = t * 8;
    int c[8], s = 0;
    #pragma unroll
    for (int i = 0; i < 8; i++) {
        const int n = base + i;
        c[i] = (n < NN) ? g_cnt[n] : 0;
        s += c[i];
    }
    tsum[t] = s;
    int v = s;
    #pragma unroll
    for (int d = 1; d < 32; d <<= 1) {
        int u = __shfl_up_sync(0xffffffffu, v, d);
        if ((t & 31) >= d) v += u;
    }
    if ((t & 31) == 31) wsum[t >> 5] = v;
    __syncthreads();
    if (t < 8) {
        int w = wsum[t];
        #pragma unroll
        for (int d = 1; d < 8; d <<= 1) {
            int u = __shfl_up_sync(0xffu, w, d);
            if (t >= d) w += u;
        }
        wsum[t] = w;
    }
    __syncthreads();
    int excl = v - s + ((t >> 5) ? wsum[(t >> 5) - 1] : 0);
    #pragma unroll
    for (int i = 0; i < 8; i++) {
        const int n = base + i;
        if (n < NN) {
            g_off[n] = excl;
            g_cur[n] = excl;
            g_dinv[n] = rsqrtf((float)(c[i] + 1));
        }
        excl += c[i];
    }
}
__global__ void csr_fill_kernel(const int* __restrict__ src, const int* __restrict__ dst) {
    int e = blockIdx.x*blockDim.x + threadIdx.x;
    if (e < EE) {
        const int p = atomicAdd(&g_cur[dst[e]], 1);
        g_esrc[p] = src[e];
    }
}

// ---------------- dual GEMM (double-buffered cp.async, dynamic smem) ----------
#define NT_DUAL ((RP + KT - 1) / KT)   // 7
__global__ __launch_bounds__(256)
void dual_gemm_kernel(const float* __restrict__ A,
                      const float* __restrict__ B1, const float* __restrict__ B2,
                      const float* __restrict__ lin_b)
{
    extern __shared__ __align__(16) float dsm[];
    // layout: As[2][KT][68], Bs1[2][KT][68], Bs2[2][KT][68]
    float (*As) [KT][68] = (float(*)[KT][68])(dsm);
    float (*Bs1)[KT][68] = (float(*)[KT][68])(dsm + 2*KT*68);
    float (*Bs2)[KT][68] = (float(*)[KT][68])(dsm + 4*KT*68);

    const int tid = threadIdx.x;
    const int tx = tid & 15, ty = tid >> 4;
    const int m0 = blockIdx.y * 64;
    const int n0 = blockIdx.x * 64;
    const int M = NN, K = RP;

    u64 accH[4][2] = {};
    u64 accX[4][2] = {};

    auto load_tile = [&](int buf, int k0) {
        #pragma unroll
        for (int p = 0; p < 8; p++) {
            const int idx = tid + p*256;
            const int m = idx >> 5, k = idx & 31;
            const int gm = m0 + m, gk = k0 + k;
            if (gm < M && gk < K)
                __pipeline_memcpy_async(&As[buf][k][m], &A[(size_t)gm*K + gk], 4);
            else
                As[buf][k][m] = 0.f;
        }
        const int r = tid >> 4, q = tid & 15;
        #pragma unroll
        for (int p = 0; p < 2; p++) {
            const int k = r + p*16;
            const int gk = k0 + k;
            if (gk < K) {
                __pipeline_memcpy_async(&Bs1[buf][k][q*4], &B1[(size_t)gk*HH + n0 + q*4], 16);
                __pipeline_memcpy_async(&Bs2[buf][k][q*4], &B2[(size_t)gk*HH + n0 + q*4], 16);
            } else {
                *(float4*)&Bs1[buf][k][q*4] = make_float4(0.f,0.f,0.f,0.f);
                *(float4*)&Bs2[buf][k][q*4] = make_float4(0.f,0.f,0.f,0.f);
            }
        }
    };

    load_tile(0, 0);
    __pipeline_commit();

    #pragma unroll 1
    for (int it = 0; it < NT_DUAL; it++) {
        __pipeline_wait_prior(0);
        __syncthreads();
        if (it + 1 < NT_DUAL) {
            load_tile((it+1) & 1, (it+1)*KT);
            __pipeline_commit();
        }
        const int cur = it & 1;
        #pragma unroll
        for (int k = 0; k < KT; k++) {
            const float4 av = *(const float4*)&As[cur][k][ty*4];
            const ulonglong2 b1 = *(const ulonglong2*)&Bs1[cur][k][tx*4];
            const ulonglong2 b2 = *(const ulonglong2*)&Bs2[cur][k][tx*4];
            u64 A2[4];
            A2[0] = pk2(av.x, av.x); A2[1] = pk2(av.y, av.y);
            A2[2] = pk2(av.z, av.z); A2[3] = pk2(av.w, av.w);
            #pragma unroll
            for (int i = 0; i < 4; i++) {
                accH[i][0] = fma2(A2[i], b1.x, accH[i][0]);
                accH[i][1] = fma2(A2[i], b1.y, accH[i][1]);
                accX[i][0] = fma2(A2[i], b2.x, accX[i][0]);
                accX[i][1] = fma2(A2[i], b2.y, accX[i][1]);
            }
        }
    }

    #pragma unroll
    for (int i = 0; i < 4; i++) {
        const int gm = m0 + ty*4 + i;
        if (gm >= M) continue;
        float h[4], xv[4];
        upk2(accH[i][0], h[0],  h[1]);  upk2(accH[i][1], h[2],  h[3]);
        upk2(accX[i][0], xv[0], xv[1]); upk2(accX[i][1], xv[2], xv[3]);
        #pragma unroll
        for (int j = 0; j < 4; j++) {
            const int gn = n0 + tx*4 + j;
            g_h [(size_t)gm*HH + gn] = h[j];
            g_xl[(size_t)gm*HH + gn] = xv[j] + lin_b[gn];
        }
    }
}
#define DUAL_SMEM (6*KT*68*(int)sizeof(float))   // 52224 bytes

// ---------------- GCN gather (CSR) + tanh(+bias) ------------------------------
#define ECH 128
__global__ __launch_bounds__(256)
void gcn_gather_kernel(const float* __restrict__ gcn_b)
{
    __shared__ int   s_src[ECH];
    __shared__ float s_w  [ECH];
    const int n = blockIdx.x;
    const int t = threadIdx.x;
    const float dn = g_dinv[n];
    const int off = g_off[n];
    const int cnt = g_cnt[n];

    const float2 hv0 = *(const float2*)&g_h[(size_t)n*HH + 2*t];
    float2 acc;
    acc.x = hv0.x * dn * dn;
    acc.y = hv0.y * dn * dn;

    for (int c0 = 0; c0 < cnt; c0 += ECH) {
        const int m = min(ECH, cnt - c0);
        __syncthreads();
        if (t < m) {
            const int s = g_esrc[off + c0 + t];
            s_src[t] = s;
            s_w[t]   = g_dinv[s] * dn;
        }
        __syncthreads();
        int j = 0;
        for (; j + 4 <= m; j += 4) {
            const int   s0 = s_src[j],   s1 = s_src[j+1], s2 = s_src[j+2], s3 = s_src[j+3];
            const float w0 = s_w[j],     w1 = s_w[j+1],   w2 = s_w[j+2],   w3 = s_w[j+3];
            const float2 h0 = *(const float2*)&g_h[(size_t)s0*HH + 2*t];
            const float2 h1 = *(const float2*)&g_h[(size_t)s1*HH + 2*t];
            const float2 h2 = *(const float2*)&g_h[(size_t)s2*HH + 2*t];
            const float2 h3 = *(const float2*)&g_h[(size_t)s3*HH + 2*t];
            acc.x = fmaf(w0, h0.x, acc.x); acc.y = fmaf(w0, h0.y, acc.y);
            acc.x = fmaf(w1, h1.x, acc.x); acc.y = fmaf(w1, h1.y, acc.y);
            acc.x = fmaf(w2, h2.x, acc.x); acc.y = fmaf(w2, h2.y, acc.y);
            acc.x = fmaf(w3, h3.x, acc.x); acc.y = fmaf(w3, h3.y, acc.y);
        }
        for (; j < m; j++) {
            const float w = s_w[j];
            const float2 h = *(const float2*)&g_h[(size_t)s_src[j]*HH + 2*t];
            acc.x = fmaf(w, h.x, acc.x);
            acc.y = fmaf(w, h.y, acc.y);
        }
    }

    float2 out;
    out.x = tanhf(acc.x + gcn_b[2*t]);
    out.y = tanhf(acc.y + gcn_b[2*t+1]);
    *(float2*)&g_z[(size_t)n*HH + 2*t] = out;
}

// ---------------- gate GEMM (double-buffered cp.async) + combine + BN ---------
#define NT_GATE (HH / KT)   // 16
__global__ __launch_bounds__(256)
void gate_gemm_kernel(const float* __restrict__ A,
                      const float* __restrict__ B,
                      const float* __restrict__ bias,
                      float* __restrict__ out)
{
    __shared__ __align__(16) float As[2][KT][68];
    __shared__ __align__(16) float Bs[2][KT][68];
    __shared__ float redS[16][64];
    __shared__ float redQ[16][64];
    const int tid = threadIdx.x;
    const int tx = tid & 15, ty = tid >> 4;
    const int m0 = blockIdx.y * 64;
    const int n0 = blockIdx.x * 64;
    const int M = NN, K = HH;

    u64 acc2[4][2] = {};

    auto load_tile = [&](int buf, int k0) {
        #pragma unroll
        for (int p = 0; p < 8; p++) {
            const int idx = tid + p*256;
            const int m = idx >> 5, k = idx & 31;
            const int gm = m0 + m;
            if (gm < M)
                __pipeline_memcpy_async(&As[buf][k][m], &A[(size_t)gm*K + k0 + k], 4);
            else
                As[buf][k][m] = 0.f;
        }
        const int r = tid >> 4, q = tid & 15;
        #pragma unroll
        for (int p = 0; p < 2; p++) {
            const int k = r + p*16;
            __pipeline_memcpy_async(&Bs[buf][k][q*4], &B[(size_t)(k0+k)*HH + n0 + q*4], 16);
        }
    };

    load_tile(0, 0);
    __pipeline_commit();

    #pragma unroll 1
    for (int it = 0; it < NT_GATE; it++) {
        __pipeline_wait_prior(0);
        __syncthreads();
        if (it + 1 < NT_GATE) {
            load_tile((it+1) & 1, (it+1)*KT);
            __pipeline_commit();
        }
        const int cur = it & 1;
        #pragma unroll
        for (int k = 0; k < KT; k++) {
            const float4 av = *(const float4*)&As[cur][k][ty*4];
            const ulonglong2 bv = *(const ulonglong2*)&Bs[cur][k][tx*4];
            u64 A2[4];
            A2[0] = pk2(av.x, av.x); A2[1] = pk2(av.y, av.y);
            A2[2] = pk2(av.z, av.z); A2[3] = pk2(av.w, av.w);
            #pragma unroll
            for (int i = 0; i < 4; i++) {
                acc2[i][0] = fma2(A2[i], bv.x, acc2[i][0]);
                acc2[i][1] = fma2(A2[i], bv.y, acc2[i][1]);
            }
        }
    }

    float cs[4] = {0.f,0.f,0.f,0.f};
    float cq[4] = {0.f,0.f,0.f,0.f};
    #pragma unroll
    for (int i = 0; i < 4; i++) {
        const int gm = m0 + ty*4 + i;
        if (gm >= M) continue;
        float av[4];
        upk2(acc2[i][0], av[0], av[1]); upk2(acc2[i][1], av[2], av[3]);
        #pragma unroll
        for (int j = 0; j < 4; j++) {
            const int gn = n0 + tx*4 + j;
            const float g  = 1.f / (1.f + expf(-(av[j] + bias[gn])));
            const float z  = A   [(size_t)gm*HH + gn];
            const float xl = g_xl[(size_t)gm*HH + gn];
            const float o  = fmaxf(fmaf(g, z - xl, xl), 0.f);
            out[(size_t)gm*HH + gn] = o;
            cs[j] += o;
            cq[j] += o*o;
        }
    }
    #pragma unroll
    for (int j = 0; j < 4; j++) {
        redS[ty][tx*4+j] = cs[j];
        redQ[ty][tx*4+j] = cq[j];
    }
    __syncthreads();
    if (tid < 64) {
        float s = 0.f, q = 0.f;
        #pragma unroll
        for (int r = 0; r < 16; r++) { s += redS[r][tid]; q += redQ[r][tid]; }
        atomicAdd(&g_colsum[n0 + tid], s);
        atomicAdd(&g_colsq [n0 + tid], q);
    }
}

// ---------------- batchnorm apply (stats computed inline) ----------------------
__global__ void bn_apply_kernel(float* __restrict__ out,
                                const float* __restrict__ gamma,
                                const float* __restrict__ beta) {
    int i = blockIdx.x*blockDim.x + threadIdx.x;
    if (i < NN*HH) {
        const int j = i & (HH-1);
        const float inv_n = 1.f / (float)NN;
        const float mean = g_colsum[j] * inv_n;
        const float var  = g_colsq[j] * inv_n - mean*mean;
        const float sc = rsqrtf(var + 1e-5f) * gamma[j];
        out[i] = fmaf(out[i] - mean, sc, beta[j]);
    }
}

// ---------------- launch ------------------------------------------------------
extern "C" void kernel_launch(void* const* d_in, const int* in_sizes, int n_in,
                              void* d_out, int out_size)
{
    const float* x      = (const float*)d_in[0];
    const int*   eidx   = (const int*)  d_in[1];
    const float* w1     = (const float*)d_in[2];
    const float* b1     = (const float*)d_in[3];
    const float* w2     = (const float*)d_in[4];
    const float* b2     = (const float*)d_in[5];
    const float* w3     = (const float*)d_in[6];
    const float* b3     = (const float*)d_in[7];
    const float* gcn_w  = (const float*)d_in[8];
    const float* gcn_b  = (const float*)d_in[9];
    const float* lin_w  = (const float*)d_in[10];
    const float* lin_b  = (const float*)d_in[11];
    const float* gate_w = (const float*)d_in[12];
    const float* gate_b = (const float*)d_in[13];
    const float* bn_g   = (const float*)d_in[14];
    const float* bn_b   = (const float*)d_in[15];
    float* out = (float*)d_out;

    const int* src = eidx;
    const int* dst = eidx + EE;

    float *p_feat, *p_z;
    cudaGetSymbolAddress((void**)&p_feat, g_feat);
    cudaGetSymbolAddress((void**)&p_z,    g_z);

    // one-time resources (no device memory involved)
    static cudaStream_t sB = nullptr;
    static cudaEvent_t  evFork = nullptr, evJoin = nullptr;
    if (!sB) {
        cudaStreamCreateWithFlags(&sB, cudaStreamNonBlocking);
        cudaEventCreateWithFlags(&evFork, cudaEventDisableTiming);
        cudaEventCreateWithFlags(&evJoin, cudaEventDisableTiming);
        cudaFuncSetAttribute(dual_gemm_kernel,
                             cudaFuncAttributeMaxDynamicSharedMemorySize, DUAL_SMEM);
    }

    // fork: CSR chain on side stream, conv+dual GEMM on main stream
    cudaEventRecord(evFork, 0);
    cudaStreamWaitEvent(sB, evFork, 0);

    csr_init_kernel <<<(NN+255)/256, 256, 0, sB>>>();
    csr_count_kernel<<<(EE+255)/256, 256, 0, sB>>>(dst);
    csr_scan_kernel <<<1, 256, 0, sB>>>();
    csr_fill_kernel <<<(EE+255)/256, 256, 0, sB>>>(src, dst);
    cudaEventRecord(evJoin, sB);

    // main stream: conv -> dual GEMM (independent of CSR)
    conv_feat_kernel<<<NN, 256>>>(x, w1, b1, w2, b2, w3, b3);
    dual_gemm_kernel<<<dim3(HH/64, (NN+63)/64), 256, DUAL_SMEM>>>(p_feat, gcn_w, lin_w, lin_b);

    // join: gather needs CSR + dinv + h
    cudaStreamWaitEvent(0, evJoin, 0);

    gcn_gather_kernel<<<NN, 256>>>(gcn_b);
    gate_gemm_kernel<<<dim3(HH/64, (NN+63)/64), 256>>>(p_z, gate_w, gate_b, out);

    // batchnorm (stats inline)
    bn_apply_kernel<<<(NN*HH+255)/256, 256>>>(out, bn_g, bn_b);
}

// round 17
// speedup vs baseline: 1.0638x; 1.0638x over previous
#include <cuda_runtime.h>
#include <cuda_pipeline.h>
#include <math.h>

// Problem constants
#define NN   2000
#define CC   4
#define LL   5000
#define EE   64000
#define HH   512
#define RP   207
#define L2O  1248          // (5000-11)/4+1
#define KT   32            // GEMM k-tile

typedef unsigned long long u64;

// ---------------- f32x2 packed helpers ---------------------------------------
__device__ __forceinline__ u64 pk2(float lo, float hi) {
    u64 r; asm("mov.b64 %0, {%1, %2};" : "=l"(r) : "f"(lo), "f"(hi)); return r;
}
__device__ __forceinline__ void upk2(u64 v, float& lo, float& hi) {
    asm("mov.b64 {%0, %1}, %2;" : "=f"(lo), "=f"(hi) : "l"(v));
}
__device__ __forceinline__ u64 fma2(u64 a, u64 b, u64 c) {
    u64 d; asm("fma.rn.f32x2 %0, %1, %2, %3;" : "=l"(d) : "l"(a), "l"(b), "l"(c));
    return d;
}

// ---------------- scratch (device globals; no runtime allocation) ------------
__device__ float g_feat[NN*RP];
__device__ float g_h  [NN*HH];
__device__ float g_z  [NN*HH];
__device__ float g_xl [NN*HH];
__device__ int   g_cnt [NN];
__device__ int   g_off [NN];
__device__ int   g_cur [NN];
__device__ int   g_esrc[EE];
__device__ float g_dinv[NN];
__device__ float g_colsum[HH];
__device__ float g_colsq [HH];

// ---------------- fused conv pipeline: x -> feat (per-node block) ------------
__global__ __launch_bounds__(256, 2)
void conv_feat_kernel(const float* __restrict__ x,
                      const float* __restrict__ w1, const float* __restrict__ b1,
                      const float* __restrict__ w2, const float* __restrict__ b2,
                      const float* __restrict__ w3, const float* __restrict__ b3)
{
    __shared__ __align__(16) float4 sw1q[16];
    __shared__ float sb1[16];
    __shared__ __align__(16) float4 sw2q[4][11];
    __shared__ float sb2[4];
    __shared__ float sw3[4][11];
    __shared__ float sb3;
    __shared__ __align__(16) float y2s[4][L2O];

    const int n    = blockIdx.x;
    const int tid  = threadIdx.x;
    const int warp = tid >> 5;
    const int lane = tid & 31;

    if (tid < 16) {
        sw1q[tid] = make_float4(w1[tid*4+0], w1[tid*4+1], w1[tid*4+2], w1[tid*4+3]);
        sb1[tid]  = b1[tid];
    }
    if (tid < 44) {
        const int c = tid / 11, k = tid % 11;
        sw2q[c][k] = make_float4(w2[0*44 + c*11 + k], w2[1*44 + c*11 + k],
                                 w2[2*44 + c*11 + k], w2[3*44 + c*11 + k]);
        sw3[c][k] = w3[tid];
    }
    if (tid < 4)   sb2[tid] = b2[tid];
    if (tid == 0)  sb3 = b3[0];
    __syncthreads();

    const float* xn = x + (size_t)n * CC * LL;

    float4 xv[4];
    {
        const int p0 = 4*(warp*30 + lane);
        const bool ld = (p0 + 3) < LL;
        #pragma unroll
        for (int c = 0; c < 4; c++)
            xv[c] = ld ? *(const float4*)&xn[c*LL + p0]
                       : make_float4(0.f, 0.f, 0.f, 0.f);
    }

    #pragma unroll 1
    for (int it = 0; it < 6; it++) {
        const int seg = it*240 + warp*30;
        const int t   = seg + lane;

        float4 xnext[4];
        if (it < 5) {
            const int p1 = 4*((it+1)*240 + warp*30 + lane);
            const bool ld1 = (p1 + 3) < LL;
            #pragma unroll
            for (int c = 0; c < 4; c++)
                xnext[c] = ld1 ? *(const float4*)&xn[c*LL + p1]
                               : make_float4(0.f, 0.f, 0.f, 0.f);
        }

        float h[4][4];
        #pragma unroll
        for (int j = 0; j < 4; j++) {
            const float x0 = ((const float*)&xv[0])[j];
            const float x1 = ((const float*)&xv[1])[j];
            const float x2 = ((const float*)&xv[2])[j];
            const float x3 = ((const float*)&xv[3])[j];
            #pragma unroll
            for (int a = 0; a < 4; a++) {
                float mx = -3.4e38f;
                #pragma unroll
                for (int b = 0; b < 4; b++) {
                    const int o = a*4 + b;
                    const float4 w = sw1q[o];
                    float pre = sb1[o];
                    pre = fmaf(x0, w.x, pre);
                    pre = fmaf(x1, w.y, pre);
                    pre = fmaf(x2, w.z, pre);
                    pre = fmaf(x3, w.w, pre);
                    mx = fmaxf(mx, pre);
                }
                h[a][j] = fmaxf(mx, 0.f);
            }
        }

        const bool emit = (lane < 30) && (t < L2O);
        float acc0 = sb2[0], acc1 = sb2[1], acc2 = sb2[2], acc3 = sb2[3];
        #pragma unroll
        for (int a = 0; a < 4; a++) {
            float hv[11];
            hv[0] = h[a][0]; hv[1] = h[a][1]; hv[2] = h[a][2]; hv[3] = h[a][3];
            hv[4]  = __shfl_down_sync(0xffffffffu, h[a][0], 1);
            hv[5]  = __shfl_down_sync(0xffffffffu, h[a][1], 1);
            hv[6]  = __shfl_down_sync(0xffffffffu, h[a][2], 1);
            hv[7]  = __shfl_down_sync(0xffffffffu, h[a][3], 1);
            hv[8]  = __shfl_down_sync(0xffffffffu, h[a][0], 2);
            hv[9]  = __shfl_down_sync(0xffffffffu, h[a][1], 2);
            hv[10] = __shfl_down_sync(0xffffffffu, h[a][2], 2);
            #pragma unroll
            for (int k = 0; k < 11; k++) {
                const float4 wq = sw2q[a][k];
                acc0 = fmaf(hv[k], wq.x, acc0);
                acc1 = fmaf(hv[k], wq.y, acc1);
                acc2 = fmaf(hv[k], wq.z, acc2);
                acc3 = fmaf(hv[k], wq.w, acc3);
            }
        }
        if (emit) {
            y2s[0][t] = fmaxf(acc0, 0.f);
            y2s[1][t] = fmaxf(acc1, 0.f);
            y2s[2][t] = fmaxf(acc2, 0.f);
            y2s[3][t] = fmaxf(acc3, 0.f);
        }

        #pragma unroll
        for (int c = 0; c < 4; c++) xv[c] = xnext[c];
    }
    __syncthreads();

    for (int t = tid; t < RP; t += 256) {
        float acc = sb3;
        #pragma unroll
        for (int c = 0; c < 4; c++)
            #pragma unroll
            for (int k = 0; k < 11; k++)
                acc = fmaf(y2s[c][6*t + k], sw3[c][k], acc);
        g_feat[(size_t)n*RP + t] = fmaxf(acc, 0.f);
    }
}

// ---------------- CSR build ---------------------------------------------------
__global__ void csr_init_kernel() {
    int i = blockIdx.x*blockDim.x + threadIdx.x;
    if (i < NN) g_cnt[i] = 0;
    if (i < HH) { g_colsum[i] = 0.f; g_colsq[i] = 0.f; }
}
__global__ void csr_count_kernel(const int* __restrict__ dst) {
    int e = blockIdx.x*blockDim.x + threadIdx.x;
    if (e < EE) atomicAdd(&g_cnt[dst[e]], 1);
}
__global__ __launch_bounds__(256)
void csr_scan_kernel() {
    __shared__ int tsum[256];
    __shared__ int wsum[8];
    const int t = threadIdx.x;
    const int base = t * 8;
    int c[8], s = 0;
    #pragma unroll
    for (int i = 0; i < 8; i++) {
        const int n = base + i;
        c[i] = (n < NN) ? g_cnt[n] : 0;
        s += c[i];
    }
    tsum[t] = s;
    int v = s;
    #pragma unroll
    for (int d = 1; d < 32; d <<= 1) {
        int u = __shfl_up_sync(0xffffffffu, v, d);
        if ((t & 31) >= d) v += u;
    }
    if ((t & 31) == 31) wsum[t >> 5] = v;
    __syncthreads();
    if (t < 8) {
        int w = wsum[t];
        #pragma unroll
        for (int d = 1; d < 8; d <<= 1) {
            int u = __shfl_up_sync(0xffu, w, d);
            if (t >= d) w += u;
        }
        wsum[t] = w;
    }
    __syncthreads();
    int excl = v - s + ((t >> 5) ? wsum[(t >> 5) - 1] : 0);
    #pragma unroll
    for (int i = 0; i < 8; i++) {
        const int n = base + i;
        if (n < NN) {
            g_off[n] = excl;
            g_cur[n] = excl;
            g_dinv[n] = rsqrtf((float)(c[i] + 1));
        }
        excl += c[i];
    }
}
__global__ void csr_fill_kernel(const int* __restrict__ src, const int* __restrict__ dst) {
    int e = blockIdx.x*blockDim.x + threadIdx.x;
    if (e < EE) {
        const int p = atomicAdd(&g_cur[dst[e]], 1);
        g_esrc[p] = src[e];
    }
}

// ---------------- dual GEMM (double-buffered cp.async, dynamic smem) ----------
#define NT_DUAL ((RP + KT - 1) / KT)   // 7
__global__ __launch_bounds__(256)
void dual_gemm_kernel(const float* __restrict__ A,
                      const float* __restrict__ B1, const float* __restrict__ B2,
                      const float* __restrict__ lin_b)
{
    extern __shared__ __align__(16) float dsm[];
    // layout: As[2][KT][68], Bs1[2][KT][68], Bs2[2][KT][68]
    float (*As) [KT][68] = (float(*)[KT][68])(dsm);
    float (*Bs1)[KT][68] = (float(*)[KT][68])(dsm + 2*KT*68);
    float (*Bs2)[KT][68] = (float(*)[KT][68])(dsm + 4*KT*68);

    const int tid = threadIdx.x;
    const int tx = tid & 15, ty = tid >> 4;
    const int m0 = blockIdx.y * 64;
    const int n0 = blockIdx.x * 64;
    const int M = NN, K = RP;

    u64 accH[4][2] = {};
    u64 accX[4][2] = {};

    auto load_tile = [&](int buf, int k0) {
        #pragma unroll
        for (int p = 0; p < 8; p++) {
            const int idx = tid + p*256;
            const int m = idx >> 5, k = idx & 31;
            const int gm = m0 + m, gk = k0 + k;
            if (gm < M && gk < K)
                __pipeline_memcpy_async(&As[buf][k][m], &A[(size_t)gm*K + gk], 4);
            else
                As[buf][k][m] = 0.f;
        }
        const int r = tid >> 4, q = tid & 15;
        #pragma unroll
        for (int p = 0; p < 2; p++) {
            const int k = r + p*16;
            const int gk = k0 + k;
            if (gk < K) {
                __pipeline_memcpy_async(&Bs1[buf][k][q*4], &B1[(size_t)gk*HH + n0 + q*4], 16);
                __pipeline_memcpy_async(&Bs2[buf][k][q*4], &B2[(size_t)gk*HH + n0 + q*4], 16);
            } else {
                *(float4*)&Bs1[buf][k][q*4] = make_float4(0.f,0.f,0.f,0.f);
                *(float4*)&Bs2[buf][k][q*4] = make_float4(0.f,0.f,0.f,0.f);
            }
        }
    };

    load_tile(0, 0);
    __pipeline_commit();

    #pragma unroll 1
    for (int it = 0; it < NT_DUAL; it++) {
        __pipeline_wait_prior(0);
        __syncthreads();
        if (it + 1 < NT_DUAL) {
            load_tile((it+1) & 1, (it+1)*KT);
            __pipeline_commit();
        }
        const int cur = it & 1;
        #pragma unroll
        for (int k = 0; k < KT; k++) {
            const float4 av = *(const float4*)&As[cur][k][ty*4];
            const ulonglong2 b1 = *(const ulonglong2*)&Bs1[cur][k][tx*4];
            const ulonglong2 b2 = *(const ulonglong2*)&Bs2[cur][k][tx*4];
            u64 A2[4];
            A2[0] = pk2(av.x, av.x); A2[1] = pk2(av.y, av.y);
            A2[2] = pk2(av.z, av.z); A2[3] = pk2(av.w, av.w);
            #pragma unroll
            for (int i = 0; i < 4; i++) {
                accH[i][0] = fma2(A2[i], b1.x, accH[i][0]);
                accH[i][1] = fma2(A2[i], b1.y, accH[i][1]);
                accX[i][0] = fma2(A2[i], b2.x, accX[i][0]);
                accX[i][1] = fma2(A2[i], b2.y, accX[i][1]);
            }
        }
    }

    #pragma unroll
    for (int i = 0; i < 4; i++) {
        const int gm = m0 + ty*4 + i;
        if (gm >= M) continue;
        float h[4], xv[4];
        upk2(accH[i][0], h[0],  h[1]);  upk2(accH[i][1], h[2],  h[3]);
        upk2(accX[i][0], xv[0], xv[1]); upk2(accX[i][1], xv[2], xv[3]);
        #pragma unroll
        for (int j = 0; j < 4; j++) {
            const int gn = n0 + tx*4 + j;
            g_h [(size_t)gm*HH + gn] = h[j];
            g_xl[(size_t)gm*HH + gn] = xv[j] + lin_b[gn];
        }
    }
}
#define DUAL_SMEM (6*KT*68*(int)sizeof(float))   // 52224 bytes

// ---------------- GCN gather (CSR) + tanh(+bias) ------------------------------
#define ECH 128
__global__ __launch_bounds__(256)
void gcn_gather_kernel(const float* __restrict__ gcn_b)
{
    __shared__ int   s_src[ECH];
    __shared__ float s_w  [ECH];
    const int n = blockIdx.x;
    const int t = threadIdx.x;
    const float dn = g_dinv[n];
    const int off = g_off[n];
    const int cnt = g_cnt[n];

    const float2 hv0 = *(const float2*)&g_h[(size_t)n*HH + 2*t];
    float2 acc;
    acc.x = hv0.x * dn * dn;
    acc.y = hv0.y * dn * dn;

    for (int c0 = 0; c0 < cnt; c0 += ECH) {
        const int m = min(ECH, cnt - c0);
        __syncthreads();
        if (t < m) {
            const int s = g_esrc[off + c0 + t];
            s_src[t] = s;
            s_w[t]   = g_dinv[s] * dn;
        }
        __syncthreads();
        int j = 0;
        for (; j + 4 <= m; j += 4) {
            const int   s0 = s_src[j],   s1 = s_src[j+1], s2 = s_src[j+2], s3 = s_src[j+3];
            const float w0 = s_w[j],     w1 = s_w[j+1],   w2 = s_w[j+2],   w3 = s_w[j+3];
            const float2 h0 = *(const float2*)&g_h[(size_t)s0*HH + 2*t];
            const float2 h1 = *(const float2*)&g_h[(size_t)s1*HH + 2*t];
            const float2 h2 = *(const float2*)&g_h[(size_t)s2*HH + 2*t];
            const float2 h3 = *(const float2*)&g_h[(size_t)s3*HH + 2*t];
            acc.x = fmaf(w0, h0.x, acc.x); acc.y = fmaf(w0, h0.y, acc.y);
            acc.x = fmaf(w1, h1.x, acc.x); acc.y = fmaf(w1, h1.y, acc.y);
            acc.x = fmaf(w2, h2.x, acc.x); acc.y = fmaf(w2, h2.y, acc.y);
            acc.x = fmaf(w3, h3.x, acc.x); acc.y = fmaf(w3, h3.y, acc.y);
        }
        for (; j < m; j++) {
            const float w = s_w[j];
            const float2 h = *(const float2*)&g_h[(size_t)s_src[j]*HH + 2*t];
            acc.x = fmaf(w, h.x, acc.x);
            acc.y = fmaf(w, h.y, acc.y);
        }
    }

    float2 out;
    out.x = tanhf(acc.x + gcn_b[2*t]);
    out.y = tanhf(acc.y + gcn_b[2*t+1]);
    *(float2*)&g_z[(size_t)n*HH + 2*t] = out;
}

// ---------------- gate GEMM (double-buffered cp.async) + combine + BN ---------
#define NT_GATE (HH / KT)   // 16
__global__ __launch_bounds__(256)
void gate_gemm_kernel(const float* __restrict__ A,
                      const float* __restrict__ B,
                      const float* __restrict__ bias,
                      float* __restrict__ out)
{
    __shared__ __align__(16) float As[2][KT][68];
    __shared__ __align__(16) float Bs[2][KT][68];
    __shared__ float redS[16][64];
    __shared__ float redQ[16][64];
    const int tid = threadIdx.x;
    const int tx = tid & 15, ty = tid >> 4;
    const int m0 = blockIdx.y * 64;
    const int n0 = blockIdx.x * 64;
    const int M = NN, K = HH;

    u64 acc2[4][2] = {};

    auto load_tile = [&](int buf, int k0) {
        #pragma unroll
        for (int p = 0; p < 8; p++) {
            const int idx = tid + p*256;
            const int m = idx >> 5, k = idx & 31;
            const int gm = m0 + m;
            if (gm < M)
                __pipeline_memcpy_async(&As[buf][k][m], &A[(size_t)gm*K + k0 + k], 4);
            else
                As[buf][k][m] = 0.f;
        }
        const int r = tid >> 4, q = tid & 15;
        #pragma unroll
        for (int p = 0; p < 2; p++) {
            const int k = r + p*16;
            __pipeline_memcpy_async(&Bs[buf][k][q*4], &B[(size_t)(k0+k)*HH + n0 + q*4], 16);
        }
    };

    load_tile(0, 0);
    __pipeline_commit();

    #pragma unroll 1
    for (int it = 0; it < NT_GATE; it++) {
        __pipeline_wait_prior(0);
        __syncthreads();
        if (it + 1 < NT_GATE) {
            load_tile((it+1) & 1, (it+1)*KT);
            __pipeline_commit();
        }
        const int cur = it & 1;
        #pragma unroll
        for (int k = 0; k < KT; k++) {
            const float4 av = *(const float4*)&As[cur][k][ty*4];
            const ulonglong2 bv = *(const ulonglong2*)&Bs[cur][k][tx*4];
            u64 A2[4];
            A2[0] = pk2(av.x, av.x); A2[1] = pk2(av.y, av.y);
            A2[2] = pk2(av.z, av.z); A2[3] = pk2(av.w, av.w);
            #pragma unroll
            for (int i = 0; i < 4; i++) {
                acc2[i][0] = fma2(A2[i], bv.x, acc2[i][0]);
                acc2[i][1] = fma2(A2[i], bv.y, acc2[i][1]);
            }
        }
    }

    float cs[4] = {0.f,0.f,0.f,0.f};
    float cq[4] = {0.f,0.f,0.f,0.f};
    #pragma unroll
    for (int i = 0; i < 4; i++) {
        const int gm = m0 + ty*4 + i;
        if (gm >= M) continue;
        float av[4];
        upk2(acc2[i][0], av[0], av[1]); upk2(acc2[i][1], av[2], av[3]);
        #pragma unroll
        for (int j = 0; j < 4; j++) {
            const int gn = n0 + tx*4 + j;
            const float g  = 1.f / (1.f + expf(-(av[j] + bias[gn])));
            const float z  = A   [(size_t)gm*HH + gn];
            const float xl = g_xl[(size_t)gm*HH + gn];
            const float o  = fmaxf(fmaf(g, z - xl, xl), 0.f);
            out[(size_t)gm*HH + gn] = o;
            cs[j] += o;
            cq[j] += o*o;
        }
    }
    #pragma unroll
    for (int j = 0; j < 4; j++) {
        redS[ty][tx*4+j] = cs[j];
        redQ[ty][tx*4+j] = cq[j];
    }
    __syncthreads();
    if (tid < 64) {
        float s = 0.f, q = 0.f;
        #pragma unroll
        for (int r = 0; r < 16; r++) { s += redS[r][tid]; q += redQ[r][tid]; }
        atomicAdd(&g_colsum[n0 + tid], s);
        atomicAdd(&g_colsq [n0 + tid], q);
    }
}

// ---------------- batchnorm apply (stats computed inline) ----------------------
__global__ void bn_apply_kernel(float* __restrict__ out,
                                const float* __restrict__ gamma,
                                const float* __restrict__ beta) {
    int i = blockIdx.x*blockDim.x + threadIdx.x;
    if (i < NN*HH) {
        const int j = i & (HH-1);
        const float inv_n = 1.f / (float)NN;
        const float mean = g_colsum[j] * inv_n;
        const float var  = g_colsq[j] * inv_n - mean*mean;
        const float sc = rsqrtf(var + 1e-5f) * gamma[j];
        out[i] = fmaf(out[i] - mean, sc, beta[j]);
    }
}

// ---------------- launch ------------------------------------------------------
extern "C" void kernel_launch(void* const* d_in, const int* in_sizes, int n_in,
                              void* d_out, int out_size)
{
    const float* x      = (const float*)d_in[0];
    const int*   eidx   = (const int*)  d_in[1];
    const float* w1     = (const float*)d_in[2];
    const float* b1     = (const float*)d_in[3];
    const float* w2     = (const float*)d_in[4];
    const float* b2     = (const float*)d_in[5];
    const float* w3     = (const float*)d_in[6];
    const float* b3     = (const float*)d_in[7];
    const float* gcn_w  = (const float*)d_in[8];
    const float* gcn_b  = (const float*)d_in[9];
    const float* lin_w  = (const float*)d_in[10];
    const float* lin_b  = (const float*)d_in[11];
    const float* gate_w = (const float*)d_in[12];
    const float* gate_b = (const float*)d_in[13];
    const float* bn_g   = (const float*)d_in[14];
    const float* bn_b   = (const float*)d_in[15];
    float* out = (float*)d_out;

    const int* src = eidx;
    const int* dst = eidx + EE;

    float *p_feat, *p_z;
    cudaGetSymbolAddress((void**)&p_feat, g_feat);
    cudaGetSymbolAddress((void**)&p_z,    g_z);

    // one-time resources (no device memory involved)
    static cudaStream_t sB = nullptr;
    static cudaEvent_t  evFork = nullptr, evJoin = nullptr;
    if (!sB) {
        cudaStreamCreateWithFlags(&sB, cudaStreamNonBlocking);
        cudaEventCreateWithFlags(&evFork, cudaEventDisableTiming);
        cudaEventCreateWithFlags(&evJoin, cudaEventDisableTiming);
        cudaFuncSetAttribute(dual_gemm_kernel,
                             cudaFuncAttributeMaxDynamicSharedMemorySize, DUAL_SMEM);
    }

    // fork: CSR chain on side stream, conv+dual GEMM on main stream
    cudaEventRecord(evFork, 0);
    cudaStreamWaitEvent(sB, evFork, 0);

    csr_init_kernel <<<(NN+255)/256, 256, 0, sB>>>();
    csr_count_kernel<<<(EE+255)/256, 256, 0, sB>>>(dst);
    csr_scan_kernel <<<1, 256, 0, sB>>>();
    csr_fill_kernel <<<(EE+255)/256, 256, 0, sB>>>(src, dst);
    cudaEventRecord(evJoin, sB);

    // main stream: conv -> dual GEMM (independent of CSR)
    conv_feat_kernel<<<NN, 256>>>(x, w1, b1, w2, b2, w3, b3);
    dual_gemm_kernel<<<dim3(HH/64, (NN+63)/64), 256, DUAL_SMEM>>>(p_feat, gcn_w, lin_w, lin_b);

    // join: gather needs CSR + dinv + h
    cudaStreamWaitEvent(0, evJoin, 0);

    gcn_gather_kernel<<<NN, 256>>>(gcn_b);
    gate_gemm_kernel<<<dim3(HH/64, (NN+63)/64), 256>>>(p_z, gate_w, gate_b, out);

    // batchnorm (stats inline)
    bn_apply_kernel<<<(NN*HH+255)/256, 256>>>(out, bn_g, bn_b);
}